// round 13
// baseline (speedup 1.0000x reference)
#include <cuda_runtime.h>
#include <cuda.h>
#include <cuda_fp16.h>
#include <cstdint>

#define BATCH 8192
#define FEAT  1024
#define NLEAF 64
#define LDIM  128
#define OUTD  8192
#define NINT  63

// ---------------- device scratch (no allocations) ----------------
__device__ __half g_xh[BATCH * FEAT];          // fp16 x, row-major [8192][1024]   (16 MB)
__device__ __half g_wh[NLEAF * LDIM * FEAT];   // fp16 W^T, [leaf][o][f]           (16 MB)
__device__ __half g_dwh[64 * FEAT];            // fp16 routing diff W, [n][f] K-major
__device__ float g_lg[BATCH * 64];             // routing logits (2 MB)
__device__ float g_lp[BATCH * 64];             // leaf probs (2 MB)

// ---------------- PTX helpers ----------------
__device__ __forceinline__ uint32_t smem_u32(const void* p) {
    uint32_t a;
    asm("{ .reg .u64 t; cvta.to.shared.u64 t, %1; cvt.u32.u64 %0, t; }" : "=r"(a) : "l"(p));
    return a;
}
__device__ __forceinline__ uint32_t elect_one() {
    uint32_t p;
    asm volatile("{\n\t.reg .pred p;\n\telect.sync _|p, 0xFFFFFFFF;\n\tselp.b32 %0, 1, 0, p;\n\t}" : "=r"(p));
    return p;
}

#define MBAR_INIT(a, c) asm volatile("mbarrier.init.shared.b64 [%0], %1;" ::"r"(a), "r"(c) : "memory")
#define MBAR_EXPECT_TX(a, n) asm volatile("mbarrier.arrive.expect_tx.shared.b64 _, [%0], %1;" ::"r"(a), "r"(n) : "memory")
#define MBAR_ARRIVE(a) asm volatile("mbarrier.arrive.shared.b64 _, [%0];" ::"r"(a) : "memory")

__device__ __forceinline__ void mbar_wait(uint32_t mbar, uint32_t parity) {
    uint32_t done;
    asm volatile(
        "{\n\t.reg .pred p;\n\t"
        "mbarrier.try_wait.parity.acquire.cta.shared::cta.b64 p, [%1], %2;\n\t"
        "selp.b32 %0, 1, 0, p;\n\t}"
        : "=r"(done) : "r"(mbar), "r"(parity) : "memory");
    if (!done) {
        asm volatile(
            "{\n\t.reg .pred P1;\n\t"
            "WL_%=:\n\t"
            "mbarrier.try_wait.parity.acquire.cta.shared::cta.b64 P1, [%0], %1, 0x989680;\n\t"
            "@P1 bra.uni WD_%=;\n\t"
            "bra.uni WL_%=;\n\t"
            "WD_%=:\n\t}"
            :: "r"(mbar), "r"(parity) : "memory");
    }
}

__device__ __forceinline__ void tma2d(uint32_t sa, const void* map, int cx, int cy, uint32_t mb) {
    asm volatile(
        "cp.async.bulk.tensor.2d.shared::cta.global.tile.mbarrier::complete_tx::bytes "
        "[%0], [%1, {%2, %3}], [%4];"
        :: "r"(sa), "l"(map), "r"(cx), "r"(cy), "r"(mb) : "memory");
}

__device__ __forceinline__ void ldm4(uint32_t* r, uint32_t addr) {
    asm volatile("ldmatrix.sync.aligned.m8n8.x4.shared.b16 {%0,%1,%2,%3}, [%4];"
        : "=r"(r[0]), "=r"(r[1]), "=r"(r[2]), "=r"(r[3]) : "r"(addr));
}
__device__ __forceinline__ void mma_f16(float* c, const uint32_t* a, uint32_t b0, uint32_t b1) {
    asm volatile(
        "mma.sync.aligned.m16n8k16.row.col.f32.f16.f16.f32 "
        "{%0,%1,%2,%3}, {%4,%5,%6,%7}, {%8,%9}, {%0,%1,%2,%3};\n"
        : "+f"(c[0]), "+f"(c[1]), "+f"(c[2]), "+f"(c[3])
        : "r"(a[0]), "r"(a[1]), "r"(a[2]), "r"(a[3]), "r"(b0), "r"(b1));
}

// ---------------- prep: fp32 -> fp16 (rn) ----------------
__global__ void k_cvt_h(const float4* __restrict__ src) {
    int i = blockIdx.x * blockDim.x + threadIdx.x;  // 2097152 threads = 8M floats
    float4 v = src[i];
    __half2 h0 = __floats2half2_rn(v.x, v.y);
    __half2 h1 = __floats2half2_rn(v.z, v.w);
    uint2 o;
    o.x = *(uint32_t*)&h0;
    o.y = *(uint32_t*)&h1;
    ((uint2*)g_xh)[i] = o;
}

// W transpose + fp16 round: lw[leaf][f][o] -> g_wh[leaf][o][f]
__global__ __launch_bounds__(256) void k_wt_h(const float* __restrict__ lw) {
    __shared__ __half sh[32][68];
    const int f0 = blockIdx.x * 64, o0 = blockIdx.y * 32, leaf = blockIdx.z;
    const int tid = threadIdx.x;
    const float* src = lw + (size_t)leaf * FEAT * LDIM;
    {
        int oj = tid & 31, fb = tid >> 5;
#pragma unroll
        for (int it = 0; it < 8; it++) {
            int fi = it * 8 + fb;
            sh[oj][fi] = __float2half_rn(src[(size_t)(f0 + fi) * LDIM + o0 + oj]);
        }
    }
    __syncthreads();
    __half* dst = g_wh + (size_t)leaf * LDIM * FEAT;
    {
        int fj = (tid & 15) * 4, ob = tid >> 4;
#pragma unroll
        for (int it = 0; it < 2; it++) {
            int oi = it * 16 + ob;
            uint2 v;
            v.x = *(const uint32_t*)&sh[oi][fj];
            v.y = *(const uint32_t*)&sh[oi][fj + 2];
            *(uint2*)(dst + (size_t)(o0 + oi) * FEAT + f0 + fj) = v;
        }
    }
}

// routing diff weights, fp16, [n][f] K-major
__global__ void k_dwh(const float* __restrict__ rw) {
    int i = blockIdx.x * blockDim.x + threadIdx.x;  // 65536
    int n = i >> 10, f = i & 1023;
    float v = 0.f;
    if (n < NINT) v = rw[(n * FEAT + f) * 2] - rw[(n * FEAT + f) * 2 + 1];
    g_dwh[n * FEAT + f] = __float2half_rn(v);
}

// ---------------- shared pipeline constants ----------------
#define BK 64
#define NSTAGE 3
#define A128_B 16384             // 128 rows x 128 bytes

// ---------------- routing GEMM (proven): fp16 mma + TMA, 128x64 tiles, 64 CTAs ----------------
#define R_BSTAGE 8192                          // 64 rows x 128 bytes
#define R_OFF_B (NSTAGE * A128_B)              // 49152
#define R_OFF_MBAR (R_OFF_B + NSTAGE * R_BSTAGE)   // 73728
#define R_SMEM (R_OFF_MBAR + 64 + 1024)

__global__ __launch_bounds__(288, 2) void k_rgemm(
    const __grid_constant__ CUtensorMap tma_a,
    const __grid_constant__ CUtensorMap tma_b)
{
    extern __shared__ char smem_raw[];
    uint32_t sb = (smem_u32(smem_raw) + 1023u) & ~1023u;
    const int tid = threadIdx.x, lane = tid & 31, wid = tid >> 5;
    const int bm0 = blockIdx.x * 128;

    if (tid == 0) {
#pragma unroll
        for (int s = 0; s < NSTAGE; s++) {
            MBAR_INIT(sb + R_OFF_MBAR + s * 8, 1);
            MBAR_INIT(sb + R_OFF_MBAR + 24 + s * 8, 256);
        }
    }
    __syncthreads();

    if (wid == 8) {
        if (elect_one()) {
            int phase = 1, slot = 0;
            for (int s = 0; s < FEAT / BK; s++) {
                mbar_wait(sb + R_OFF_MBAR + 24 + slot * 8, phase);
                MBAR_EXPECT_TX(sb + R_OFF_MBAR + slot * 8, A128_B + R_BSTAGE);
                tma2d(sb + slot * A128_B, &tma_a, s * BK, bm0, sb + R_OFF_MBAR + slot * 8);
                tma2d(sb + R_OFF_B + slot * R_BSTAGE, &tma_b, s * BK, 0,
                      sb + R_OFF_MBAR + slot * 8);
                if (++slot == NSTAGE) { slot = 0; phase ^= 1; }
            }
        }
        return;
    }

    const int mw = wid * 16;
    const int g = lane >> 2, cc = lane & 3;
    const int lr = lane & 7, grp = lane >> 3;
    const uint32_t xr = (uint32_t)lr << 4;
    const uint32_t a_rbase = (mw + (grp & 1) * 8 + lr) * 128;
    const uint32_t b_rbase = ((grp >> 1) * 8 + lr) * 128;
    const uint32_t a_cb0 = (uint32_t)(grp >> 1) * 16;
    const uint32_t b_cb0 = (uint32_t)(grp & 1) * 16;

    float acc[8][4];
#pragma unroll
    for (int b = 0; b < 8; b++)
#pragma unroll
        for (int c = 0; c < 4; c++) acc[b][c] = 0.f;

    int phase = 0, slot = 0;
    for (int kt = 0; kt < FEAT / BK; kt++) {
        mbar_wait(sb + R_OFF_MBAR + slot * 8, phase);
        uint32_t abase = sb + slot * A128_B + a_rbase;
        uint32_t bbase = sb + R_OFF_B + slot * R_BSTAGE + b_rbase;
#pragma unroll
        for (int ks = 0; ks < 4; ks++) {
            uint32_t acb = (a_cb0 + ks * 32) ^ xr;
            uint32_t bcb = (b_cb0 + ks * 32) ^ xr;
            uint32_t a[4], b[4][4];
            ldm4(a, abase + acb);
#pragma unroll
            for (int pn = 0; pn < 4; pn++)
                ldm4(b[pn], bbase + pn * 16 * 128 + bcb);
#pragma unroll
            for (int nt = 0; nt < 8; nt++) {
                int pn = nt >> 1, hi = (nt & 1) << 1;
                mma_f16(acc[nt], a, b[pn][hi], b[pn][hi + 1]);
            }
        }
        MBAR_ARRIVE(sb + R_OFF_MBAR + 24 + slot * 8);
        if (++slot == NSTAGE) { slot = 0; phase ^= 1; }
    }

    int r0 = bm0 + mw + g;
#pragma unroll
    for (int nt = 0; nt < 8; nt++) {
        int col = nt * 8 + 2 * cc;
        *(float2*)(g_lg + (size_t)r0 * 64 + col) = make_float2(acc[nt][0], acc[nt][1]);
        *(float2*)(g_lg + (size_t)(r0 + 8) * 64 + col) = make_float2(acc[nt][2], acc[nt][3]);
    }
}

// ---------------- leaf probs ----------------
__global__ void k_leaf() {
    __shared__ float ps[8][64];
    int tid = threadIdx.x;  // 512
    int rb = blockIdx.x * 8;
    int r = tid >> 6, n = tid & 63;
    if (n < NINT) {
        float s = g_lg[(size_t)(rb + r) * 64 + n];
        ps[r][n] = 1.f / (1.f + __expf(-s));
    }
    __syncthreads();
    int l = n;
    float prob = 1.f;
#pragma unroll
    for (int d = 0; d < 6; d++) {
        int node = (1 << d) - 1 + (l >> (6 - d));
        int dir = (l >> (5 - d)) & 1;
        float p = ps[r][node];
        prob *= dir ? (1.f - p) : p;
    }
    g_lp[(size_t)(rb + r) * 64 + l] = prob;
}

// ---------------- main GEMM: 256x128 CTA tile, 16 consumer warps of 32x64 (R6 body), 3-stage ----------------
#define A_STG_B 32768                       // 256 rows x 128 bytes
#define B_STG_B 16384                       // 128 rows x 128 bytes
#define OFF_BSTG (NSTAGE * A_STG_B)         // 98304
#define OFF_MBAR (OFF_BSTG + NSTAGE * B_STG_B)  // 147456: full[3], empty[3]
#define SMEM_RAW (OFF_MBAR + 64 + 1024)

__global__ __launch_bounds__(544, 1) void k_main(
    const __grid_constant__ CUtensorMap tma_a,
    const __grid_constant__ CUtensorMap tma_b,
    const float* __restrict__ bias, float* __restrict__ out)
{
    extern __shared__ char smem_raw[];
    uint32_t sb = (smem_u32(smem_raw) + 1023u) & ~1023u;
    const int tid = threadIdx.x, lane = tid & 31, wid = tid >> 5;
    const int leaf = blockIdx.x;
    const int bm0 = blockIdx.y * 256;

    if (tid == 0) {
#pragma unroll
        for (int s = 0; s < NSTAGE; s++) {
            MBAR_INIT(sb + OFF_MBAR + s * 8, 1);
            MBAR_INIT(sb + OFF_MBAR + 24 + s * 8, 512);
        }
    }
    __syncthreads();

    if (wid == 16) {
        if (elect_one()) {
            int phase = 1, slot = 0;
            for (int s = 0; s < FEAT / BK; s++) {
                mbar_wait(sb + OFF_MBAR + 24 + slot * 8, phase);
                MBAR_EXPECT_TX(sb + OFF_MBAR + slot * 8, A_STG_B + B_STG_B);
                tma2d(sb + slot * A_STG_B, &tma_a, s * BK, bm0, sb + OFF_MBAR + slot * 8);
                tma2d(sb + OFF_BSTG + slot * B_STG_B, &tma_b, s * BK, leaf * 128,
                      sb + OFF_MBAR + slot * 8);
                if (++slot == NSTAGE) { slot = 0; phase ^= 1; }
            }
        }
        return;
    }

    // 16 consumer warps: R6-exact 32x64 warp body; warps 8-15 take rows 128-255
    const int w8 = wid & 7;
    const int mw = (wid >> 3) * 128 + (w8 & 3) * 32, nw = (w8 >> 2) * 64;
    const int g = lane >> 2, cc = lane & 3;
    const int lr = lane & 7, grp = lane >> 3;
    const uint32_t xr = (uint32_t)lr << 4;
    const uint32_t a_rbase = (mw + (grp & 1) * 8 + lr) * 128;
    const uint32_t b_rbase = (nw + (grp >> 1) * 8 + lr) * 128;
    const uint32_t a_cb0 = (uint32_t)(grp >> 1) * 16;
    const uint32_t b_cb0 = (uint32_t)(grp & 1) * 16;

    float acc[2][8][4];
#pragma unroll
    for (int a = 0; a < 2; a++)
#pragma unroll
        for (int b = 0; b < 8; b++)
#pragma unroll
            for (int c = 0; c < 4; c++) acc[a][b][c] = 0.f;

    int phase = 0, slot = 0;
    for (int kt = 0; kt < FEAT / BK; kt++) {
        mbar_wait(sb + OFF_MBAR + slot * 8, phase);
        uint32_t abase = sb + slot * A_STG_B + a_rbase;
        uint32_t bbase = sb + OFF_BSTG + slot * B_STG_B + b_rbase;
#pragma unroll
        for (int ks = 0; ks < 4; ks++) {
            uint32_t acb = (a_cb0 + ks * 32) ^ xr;
            uint32_t bcb = (b_cb0 + ks * 32) ^ xr;
            uint32_t a[2][4], b[4][4];
            ldm4(a[0], abase + acb);
            ldm4(a[1], abase + 16 * 128 + acb);
#pragma unroll
            for (int pn = 0; pn < 4; pn++)
                ldm4(b[pn], bbase + pn * 16 * 128 + bcb);
#pragma unroll
            for (int nt = 0; nt < 8; nt++) {
                int pn = nt >> 1, hi = (nt & 1) << 1;
                mma_f16(acc[0][nt], a[0], b[pn][hi], b[pn][hi + 1]);
                mma_f16(acc[1][nt], a[1], b[pn][hi], b[pn][hi + 1]);
            }
        }
        MBAR_ARRIVE(sb + OFF_MBAR + 24 + slot * 8);
        if (++slot == NSTAGE) { slot = 0; phase ^= 1; }
    }

#pragma unroll
    for (int mt = 0; mt < 2; mt++) {
        int r0 = bm0 + mw + mt * 16 + g;
        float p0 = g_lp[(size_t)r0 * 64 + leaf];
        float p1 = g_lp[(size_t)(r0 + 8) * 64 + leaf];
#pragma unroll
        for (int nt = 0; nt < 8; nt++) {
            int col = nw + nt * 8 + 2 * cc;
            float b0 = bias[leaf * LDIM + col];
            float b1 = bias[leaf * LDIM + col + 1];
            int gc = leaf * LDIM + col;
            float2 v0 = make_float2(p0 * (acc[mt][nt][0] + b0), p0 * (acc[mt][nt][1] + b1));
            float2 v1 = make_float2(p1 * (acc[mt][nt][2] + b0), p1 * (acc[mt][nt][3] + b1));
            *(float2*)(out + (size_t)r0 * OUTD + gc) = v0;
            *(float2*)(out + (size_t)(r0 + 8) * OUTD + gc) = v1;
        }
    }
}

// ---------------- host ----------------
typedef CUresult (*PFN_encodeTiled)(CUtensorMap*, CUtensorMapDataType, cuuint32_t, void*,
                                    const cuuint64_t*, const cuuint64_t*, const cuuint32_t*,
                                    const cuuint32_t*, CUtensorMapInterleave, CUtensorMapSwizzle,
                                    CUtensorMapL2promotion, CUtensorMapFloatOOBfill);

static void make_map(PFN_encodeTiled enc, CUtensorMap* m, void* base,
                     cuuint64_t rows, cuuint32_t box_rows) {
    cuuint64_t dims[2] = {FEAT, rows};
    cuuint64_t strides[1] = {FEAT * sizeof(__half)};
    cuuint32_t box[2] = {BK, box_rows};
    cuuint32_t es[2] = {1, 1};
    enc(m, CU_TENSOR_MAP_DATA_TYPE_UINT16, 2, base, dims, strides, box, es,
        CU_TENSOR_MAP_INTERLEAVE_NONE, CU_TENSOR_MAP_SWIZZLE_128B,
        CU_TENSOR_MAP_L2_PROMOTION_L2_128B, CU_TENSOR_MAP_FLOAT_OOB_FILL_NONE);
}

extern "C" void kernel_launch(void* const* d_in, const int* in_sizes, int n_in,
                              void* d_out, int out_size) {
    const float* x  = (const float*)d_in[0];
    const float* rw = (const float*)d_in[1];
    const float* lw = (const float*)d_in[2];
    const float* lb = (const float*)d_in[3];
    float* out = (float*)d_out;
    (void)in_sizes; (void)n_in; (void)out_size;

    PFN_encodeTiled enc = nullptr;
    cudaDriverEntryPointQueryResult qr;
    cudaGetDriverEntryPoint("cuTensorMapEncodeTiled", (void**)&enc, cudaEnableDefault, &qr);

    void* xh_ptr = nullptr; void* wh_ptr = nullptr; void* dwh_ptr = nullptr;
    cudaGetSymbolAddress(&xh_ptr, g_xh);
    cudaGetSymbolAddress(&wh_ptr, g_wh);
    cudaGetSymbolAddress(&dwh_ptr, g_dwh);

    CUtensorMap tma_a128, tma_a256, tma_b, tma_d;
    make_map(enc, &tma_a128, xh_ptr, 8192, 128);   // k_rgemm A
    make_map(enc, &tma_a256, xh_ptr, 8192, 256);   // k_main A (256-row box)
    make_map(enc, &tma_b, wh_ptr, 8192, 128);      // k_main B (one leaf = 128 rows)
    make_map(enc, &tma_d, dwh_ptr, 64, 64);

    cudaFuncSetAttribute(k_main, cudaFuncAttributeMaxDynamicSharedMemorySize, SMEM_RAW);
    cudaFuncSetAttribute(k_rgemm, cudaFuncAttributeMaxDynamicSharedMemorySize, R_SMEM);

    // single-stream chain (deterministic, capture-safe)
    k_cvt_h<<<8192, 256>>>((const float4*)x);
    k_wt_h<<<dim3(16, 4, 64), 256>>>(lw);
    k_dwh<<<256, 256>>>(rw);
    k_rgemm<<<64, 288, R_SMEM>>>(tma_a128, tma_d);
    k_leaf<<<1024, 512>>>();
    k_main<<<dim3(64, 32), 544, SMEM_RAW>>>(tma_a256, tma_b, lb, out);
}

// round 15
// speedup vs baseline: 1.0394x; 1.0394x over previous
#include <cuda_runtime.h>
#include <cuda.h>
#include <cuda_fp16.h>
#include <cstdint>

#define BATCH 8192
#define FEAT  1024
#define NLEAF 64
#define LDIM  128
#define OUTD  8192
#define NINT  63

// ---------------- device scratch (no allocations) ----------------
__device__ __half g_xh[BATCH * FEAT];          // fp16 x, row-major [8192][1024]   (16 MB)
__device__ __half g_wh[NLEAF * LDIM * FEAT];   // fp16 W^T, [leaf][o][f]           (16 MB)
__device__ __half g_dwh[64 * FEAT];            // fp16 routing diff W, [n][f] K-major
__device__ float g_part[2][BATCH * 64];        // routing logit partials (4 MB)
__device__ float g_lp[BATCH * 64];             // leaf probs (2 MB)

// ---------------- PTX helpers ----------------
__device__ __forceinline__ uint32_t smem_u32(const void* p) {
    uint32_t a;
    asm("{ .reg .u64 t; cvta.to.shared.u64 t, %1; cvt.u32.u64 %0, t; }" : "=r"(a) : "l"(p));
    return a;
}
__device__ __forceinline__ uint32_t elect_one() {
    uint32_t p;
    asm volatile("{\n\t.reg .pred p;\n\telect.sync _|p, 0xFFFFFFFF;\n\tselp.b32 %0, 1, 0, p;\n\t}" : "=r"(p));
    return p;
}

#define MBAR_INIT(a, c) asm volatile("mbarrier.init.shared.b64 [%0], %1;" ::"r"(a), "r"(c) : "memory")
#define MBAR_EXPECT_TX(a, n) asm volatile("mbarrier.arrive.expect_tx.shared.b64 _, [%0], %1;" ::"r"(a), "r"(n) : "memory")
#define MBAR_ARRIVE(a) asm volatile("mbarrier.arrive.shared.b64 _, [%0];" ::"r"(a) : "memory")

__device__ __forceinline__ void mbar_wait(uint32_t mbar, uint32_t parity) {
    uint32_t done;
    asm volatile(
        "{\n\t.reg .pred p;\n\t"
        "mbarrier.try_wait.parity.acquire.cta.shared::cta.b64 p, [%1], %2;\n\t"
        "selp.b32 %0, 1, 0, p;\n\t}"
        : "=r"(done) : "r"(mbar), "r"(parity) : "memory");
    if (!done) {
        asm volatile(
            "{\n\t.reg .pred P1;\n\t"
            "WL_%=:\n\t"
            "mbarrier.try_wait.parity.acquire.cta.shared::cta.b64 P1, [%0], %1, 0x989680;\n\t"
            "@P1 bra.uni WD_%=;\n\t"
            "bra.uni WL_%=;\n\t"
            "WD_%=:\n\t}"
            :: "r"(mbar), "r"(parity) : "memory");
    }
}

__device__ __forceinline__ void tma2d(uint32_t sa, const void* map, int cx, int cy, uint32_t mb) {
    asm volatile(
        "cp.async.bulk.tensor.2d.shared::cta.global.tile.mbarrier::complete_tx::bytes "
        "[%0], [%1, {%2, %3}], [%4];"
        :: "r"(sa), "l"(map), "r"(cx), "r"(cy), "r"(mb) : "memory");
}

__device__ __forceinline__ void ldm4(uint32_t* r, uint32_t addr) {
    asm volatile("ldmatrix.sync.aligned.m8n8.x4.shared.b16 {%0,%1,%2,%3}, [%4];"
        : "=r"(r[0]), "=r"(r[1]), "=r"(r[2]), "=r"(r[3]) : "r"(addr));
}
__device__ __forceinline__ void mma_f16(float* c, const uint32_t* a, uint32_t b0, uint32_t b1) {
    asm volatile(
        "mma.sync.aligned.m16n8k16.row.col.f32.f16.f16.f32 "
        "{%0,%1,%2,%3}, {%4,%5,%6,%7}, {%8,%9}, {%0,%1,%2,%3};\n"
        : "+f"(c[0]), "+f"(c[1]), "+f"(c[2]), "+f"(c[3])
        : "r"(a[0]), "r"(a[1]), "r"(a[2]), "r"(a[3]), "r"(b0), "r"(b1));
}

// ---------------- prep: fp32 -> fp16 (rn) ----------------
__global__ void k_cvt_h(const float4* __restrict__ src) {
    int i = blockIdx.x * blockDim.x + threadIdx.x;  // 2097152 threads = 8M floats
    float4 v = src[i];
    __half2 h0 = __floats2half2_rn(v.x, v.y);
    __half2 h1 = __floats2half2_rn(v.z, v.w);
    uint2 o;
    o.x = *(uint32_t*)&h0;
    o.y = *(uint32_t*)&h1;
    ((uint2*)g_xh)[i] = o;
}

// W transpose + fp16 round: lw[leaf][f][o] -> g_wh[leaf][o][f]
__global__ __launch_bounds__(256) void k_wt_h(const float* __restrict__ lw) {
    __shared__ __half sh[32][68];
    const int f0 = blockIdx.x * 64, o0 = blockIdx.y * 32, leaf = blockIdx.z;
    const int tid = threadIdx.x;
    const float* src = lw + (size_t)leaf * FEAT * LDIM;
    {
        int oj = tid & 31, fb = tid >> 5;
#pragma unroll
        for (int it = 0; it < 8; it++) {
            int fi = it * 8 + fb;
            sh[oj][fi] = __float2half_rn(src[(size_t)(f0 + fi) * LDIM + o0 + oj]);
        }
    }
    __syncthreads();
    __half* dst = g_wh + (size_t)leaf * LDIM * FEAT;
    {
        int fj = (tid & 15) * 4, ob = tid >> 4;
#pragma unroll
        for (int it = 0; it < 2; it++) {
            int oi = it * 16 + ob;
            uint2 v;
            v.x = *(const uint32_t*)&sh[oi][fj];
            v.y = *(const uint32_t*)&sh[oi][fj + 2];
            *(uint2*)(dst + (size_t)(o0 + oi) * FEAT + f0 + fj) = v;
        }
    }
}

// routing diff weights, fp16, [n][f] K-major
__global__ void k_dwh(const float* __restrict__ rw) {
    int i = blockIdx.x * blockDim.x + threadIdx.x;  // 65536
    int n = i >> 10, f = i & 1023;
    float v = 0.f;
    if (n < NINT) v = rw[(n * FEAT + f) * 2] - rw[(n * FEAT + f) * 2 + 1];
    g_dwh[n * FEAT + f] = __float2half_rn(v);
}

// ---------------- shared pipeline constants ----------------
#define BK 64
#define NSTAGE 3
#define A128_B 16384             // 128 rows x 128 bytes

// ---------------- routing GEMM: proven 288-thread body, split-K x2 (grid 64x2) ----------------
#define R_BSTAGE 8192                          // 64 rows x 128 bytes
#define R_OFF_B (NSTAGE * A128_B)              // 49152
#define R_OFF_MBAR (R_OFF_B + NSTAGE * R_BSTAGE)   // 73728
#define R_SMEM (R_OFF_MBAR + 64 + 1024)

__global__ __launch_bounds__(288, 2) void k_rgemm(
    const __grid_constant__ CUtensorMap tma_a,
    const __grid_constant__ CUtensorMap tma_b)
{
    extern __shared__ char smem_raw[];
    uint32_t sb = (smem_u32(smem_raw) + 1023u) & ~1023u;
    const int tid = threadIdx.x, lane = tid & 31, wid = tid >> 5;
    const int bm0 = blockIdx.x * 128;
    const int kb0 = blockIdx.y * 512;          // split-K base
    const int KT = (FEAT / 2) / BK;            // 8

    if (tid == 0) {
#pragma unroll
        for (int s = 0; s < NSTAGE; s++) {
            MBAR_INIT(sb + R_OFF_MBAR + s * 8, 1);
            MBAR_INIT(sb + R_OFF_MBAR + 24 + s * 8, 256);
        }
    }
    __syncthreads();

    if (wid == 8) {
        if (elect_one()) {
            int phase = 1, slot = 0;
            for (int s = 0; s < KT; s++) {
                mbar_wait(sb + R_OFF_MBAR + 24 + slot * 8, phase);
                MBAR_EXPECT_TX(sb + R_OFF_MBAR + slot * 8, A128_B + R_BSTAGE);
                tma2d(sb + slot * A128_B, &tma_a, kb0 + s * BK, bm0, sb + R_OFF_MBAR + slot * 8);
                tma2d(sb + R_OFF_B + slot * R_BSTAGE, &tma_b, kb0 + s * BK, 0,
                      sb + R_OFF_MBAR + slot * 8);
                if (++slot == NSTAGE) { slot = 0; phase ^= 1; }
            }
        }
        return;
    }

    const int mw = wid * 16;
    const int g = lane >> 2, cc = lane & 3;
    const int lr = lane & 7, grp = lane >> 3;
    const uint32_t xr = (uint32_t)lr << 4;
    const uint32_t a_rbase = (mw + (grp & 1) * 8 + lr) * 128;
    const uint32_t b_rbase = ((grp >> 1) * 8 + lr) * 128;
    const uint32_t a_cb0 = (uint32_t)(grp >> 1) * 16;
    const uint32_t b_cb0 = (uint32_t)(grp & 1) * 16;

    float acc[8][4];
#pragma unroll
    for (int b = 0; b < 8; b++)
#pragma unroll
        for (int c = 0; c < 4; c++) acc[b][c] = 0.f;

    int phase = 0, slot = 0;
    for (int kt = 0; kt < KT; kt++) {
        mbar_wait(sb + R_OFF_MBAR + slot * 8, phase);
        uint32_t abase = sb + slot * A128_B + a_rbase;
        uint32_t bbase = sb + R_OFF_B + slot * R_BSTAGE + b_rbase;
#pragma unroll
        for (int ks = 0; ks < 4; ks++) {
            uint32_t acb = (a_cb0 + ks * 32) ^ xr;
            uint32_t bcb = (b_cb0 + ks * 32) ^ xr;
            uint32_t a[4], b[4][4];
            ldm4(a, abase + acb);
#pragma unroll
            for (int pn = 0; pn < 4; pn++)
                ldm4(b[pn], bbase + pn * 16 * 128 + bcb);
#pragma unroll
            for (int nt = 0; nt < 8; nt++) {
                int pn = nt >> 1, hi = (nt & 1) << 1;
                mma_f16(acc[nt], a, b[pn][hi], b[pn][hi + 1]);
            }
        }
        MBAR_ARRIVE(sb + R_OFF_MBAR + 24 + slot * 8);
        if (++slot == NSTAGE) { slot = 0; phase ^= 1; }
    }

    float* dst = g_part[blockIdx.y];
    int r0 = bm0 + mw + g;
#pragma unroll
    for (int nt = 0; nt < 8; nt++) {
        int col = nt * 8 + 2 * cc;
        *(float2*)(dst + (size_t)r0 * 64 + col) = make_float2(acc[nt][0], acc[nt][1]);
        *(float2*)(dst + (size_t)(r0 + 8) * 64 + col) = make_float2(acc[nt][2], acc[nt][3]);
    }
}

// ---------------- leaf probs (separate proven kernel; sums split-K partials) ----------------
__global__ void k_leaf() {
    __shared__ float ps[8][64];
    int tid = threadIdx.x;  // 512
    int rb = blockIdx.x * 8;
    int r = tid >> 6, n = tid & 63;
    if (n < NINT) {
        size_t idx = (size_t)(rb + r) * 64 + n;
        float s = g_part[0][idx] + g_part[1][idx];
        ps[r][n] = 1.f / (1.f + __expf(-s));
    }
    __syncthreads();
    int l = n;
    float prob = 1.f;
#pragma unroll
    for (int d = 0; d < 6; d++) {
        int node = (1 << d) - 1 + (l >> (6 - d));
        int dir = (l >> (5 - d)) & 1;
        float p = ps[r][node];
        prob *= dir ? (1.f - p) : p;
    }
    g_lp[(size_t)(rb + r) * 64 + l] = prob;
}

// ---------------- main GEMM (R11-exact): fp16 mma.sync + TMA, 8 warps of 32x64 ----------------
#define OFF_BSTG (NSTAGE * A128_B)         // 49152
#define OFF_MBAR (2 * NSTAGE * A128_B)     // 98304: full[3], empty[3]
#define SMEM_RAW (OFF_MBAR + 64 + 1024)

__global__ __launch_bounds__(288, 2) void k_main(
    const __grid_constant__ CUtensorMap tma_a,
    const __grid_constant__ CUtensorMap tma_b,
    const float* __restrict__ bias, float* __restrict__ out)
{
    extern __shared__ char smem_raw[];
    uint32_t sb = (smem_u32(smem_raw) + 1023u) & ~1023u;
    const int tid = threadIdx.x, lane = tid & 31, wid = tid >> 5;
    const int leaf = blockIdx.x;
    const int bm0 = blockIdx.y * 128;

    if (tid == 0) {
#pragma unroll
        for (int s = 0; s < NSTAGE; s++) {
            MBAR_INIT(sb + OFF_MBAR + s * 8, 1);
            MBAR_INIT(sb + OFF_MBAR + 24 + s * 8, 256);
        }
    }
    __syncthreads();

    if (wid == 8) {
        if (elect_one()) {
            int phase = 1, slot = 0;
            for (int s = 0; s < FEAT / BK; s++) {
                mbar_wait(sb + OFF_MBAR + 24 + slot * 8, phase);
                MBAR_EXPECT_TX(sb + OFF_MBAR + slot * 8, 2 * A128_B);
                tma2d(sb + slot * A128_B, &tma_a, s * BK, bm0, sb + OFF_MBAR + slot * 8);
                tma2d(sb + OFF_BSTG + slot * A128_B, &tma_b, s * BK, leaf * 128,
                      sb + OFF_MBAR + slot * 8);
                if (++slot == NSTAGE) { slot = 0; phase ^= 1; }
            }
        }
        return;
    }

    // 8 compute warps: 32x64 tile each (proven body)
    const int mw = (wid & 3) * 32, nw = (wid >> 2) * 64;
    const int g = lane >> 2, cc = lane & 3;
    const int lr = lane & 7, grp = lane >> 3;
    const uint32_t xr = (uint32_t)lr << 4;
    const uint32_t a_rbase = (mw + (grp & 1) * 8 + lr) * 128;
    const uint32_t b_rbase = (nw + (grp >> 1) * 8 + lr) * 128;
    const uint32_t a_cb0 = (uint32_t)(grp >> 1) * 16;
    const uint32_t b_cb0 = (uint32_t)(grp & 1) * 16;

    float acc[2][8][4];
#pragma unroll
    for (int a = 0; a < 2; a++)
#pragma unroll
        for (int b = 0; b < 8; b++)
#pragma unroll
            for (int c = 0; c < 4; c++) acc[a][b][c] = 0.f;

    int phase = 0, slot = 0;
    for (int kt = 0; kt < FEAT / BK; kt++) {
        mbar_wait(sb + OFF_MBAR + slot * 8, phase);
        uint32_t abase = sb + slot * A128_B + a_rbase;
        uint32_t bbase = sb + OFF_BSTG + slot * A128_B + b_rbase;
#pragma unroll
        for (int ks = 0; ks < 4; ks++) {
            uint32_t acb = (a_cb0 + ks * 32) ^ xr;
            uint32_t bcb = (b_cb0 + ks * 32) ^ xr;
            uint32_t a[2][4], b[4][4];
            ldm4(a[0], abase + acb);
            ldm4(a[1], abase + 16 * 128 + acb);
#pragma unroll
            for (int pn = 0; pn < 4; pn++)
                ldm4(b[pn], bbase + pn * 16 * 128 + bcb);
#pragma unroll
            for (int nt = 0; nt < 8; nt++) {
                int pn = nt >> 1, hi = (nt & 1) << 1;
                mma_f16(acc[0][nt], a[0], b[pn][hi], b[pn][hi + 1]);
                mma_f16(acc[1][nt], a[1], b[pn][hi], b[pn][hi + 1]);
            }
        }
        MBAR_ARRIVE(sb + OFF_MBAR + 24 + slot * 8);
        if (++slot == NSTAGE) { slot = 0; phase ^= 1; }
    }

#pragma unroll
    for (int mt = 0; mt < 2; mt++) {
        int r0 = bm0 + mw + mt * 16 + g;
        float p0 = g_lp[(size_t)r0 * 64 + leaf];
        float p1 = g_lp[(size_t)(r0 + 8) * 64 + leaf];
#pragma unroll
        for (int nt = 0; nt < 8; nt++) {
            int col = nw + nt * 8 + 2 * cc;
            float b0 = bias[leaf * LDIM + col];
            float b1 = bias[leaf * LDIM + col + 1];
            int gc = leaf * LDIM + col;
            float2 v0 = make_float2(p0 * (acc[mt][nt][0] + b0), p0 * (acc[mt][nt][1] + b1));
            float2 v1 = make_float2(p1 * (acc[mt][nt][2] + b0), p1 * (acc[mt][nt][3] + b1));
            *(float2*)(out + (size_t)r0 * OUTD + gc) = v0;
            *(float2*)(out + (size_t)(r0 + 8) * OUTD + gc) = v1;
        }
    }
}

// ---------------- host ----------------
typedef CUresult (*PFN_encodeTiled)(CUtensorMap*, CUtensorMapDataType, cuuint32_t, void*,
                                    const cuuint64_t*, const cuuint64_t*, const cuuint32_t*,
                                    const cuuint32_t*, CUtensorMapInterleave, CUtensorMapSwizzle,
                                    CUtensorMapL2promotion, CUtensorMapFloatOOBfill);

static void make_map(PFN_encodeTiled enc, CUtensorMap* m, void* base,
                     cuuint64_t rows, cuuint32_t box_rows) {
    cuuint64_t dims[2] = {FEAT, rows};
    cuuint64_t strides[1] = {FEAT * sizeof(__half)};
    cuuint32_t box[2] = {BK, box_rows};
    cuuint32_t es[2] = {1, 1};
    enc(m, CU_TENSOR_MAP_DATA_TYPE_UINT16, 2, base, dims, strides, box, es,
        CU_TENSOR_MAP_INTERLEAVE_NONE, CU_TENSOR_MAP_SWIZZLE_128B,
        CU_TENSOR_MAP_L2_PROMOTION_L2_128B, CU_TENSOR_MAP_FLOAT_OOB_FILL_NONE);
}

extern "C" void kernel_launch(void* const* d_in, const int* in_sizes, int n_in,
                              void* d_out, int out_size) {
    const float* x  = (const float*)d_in[0];
    const float* rw = (const float*)d_in[1];
    const float* lw = (const float*)d_in[2];
    const float* lb = (const float*)d_in[3];
    float* out = (float*)d_out;
    (void)in_sizes; (void)n_in; (void)out_size;

    PFN_encodeTiled enc = nullptr;
    cudaDriverEntryPointQueryResult qr;
    cudaGetDriverEntryPoint("cuTensorMapEncodeTiled", (void**)&enc, cudaEnableDefault, &qr);

    void* xh_ptr = nullptr; void* wh_ptr = nullptr; void* dwh_ptr = nullptr;
    cudaGetSymbolAddress(&xh_ptr, g_xh);
    cudaGetSymbolAddress(&wh_ptr, g_wh);
    cudaGetSymbolAddress(&dwh_ptr, g_dwh);

    CUtensorMap tma_a, tma_b, tma_d;
    make_map(enc, &tma_a, xh_ptr, 8192, 128);
    make_map(enc, &tma_b, wh_ptr, 8192, 128);
    make_map(enc, &tma_d, dwh_ptr, 64, 64);

    cudaFuncSetAttribute(k_main, cudaFuncAttributeMaxDynamicSharedMemorySize, SMEM_RAW);
    cudaFuncSetAttribute(k_rgemm, cudaFuncAttributeMaxDynamicSharedMemorySize, R_SMEM);

    // single-stream chain (deterministic, capture-safe)
    k_cvt_h<<<8192, 256>>>((const float4*)x);
    k_wt_h<<<dim3(16, 4, 64), 256>>>(lw);
    k_dwh<<<256, 256>>>(rw);
    k_rgemm<<<dim3(64, 2), 288, R_SMEM>>>(tma_a, tma_d);
    k_leaf<<<1024, 512>>>();
    k_main<<<dim3(64, 64), 288, SMEM_RAW>>>(tma_a, tma_b, lb, out);
}

// round 16
// speedup vs baseline: 1.0453x; 1.0057x over previous
#include <cuda_runtime.h>
#include <cuda.h>
#include <cuda_fp16.h>
#include <cstdint>

#define BATCH 8192
#define FEAT  1024
#define NLEAF 64
#define LDIM  128
#define OUTD  8192
#define NINT  63

// ---------------- device scratch (no allocations) ----------------
__device__ __half g_xh[BATCH * FEAT];          // fp16 x, row-major [8192][1024]   (16 MB)
__device__ __half g_wh[NLEAF * LDIM * FEAT];   // fp16 W^T, [leaf][o][f]           (16 MB)
__device__ __half g_dwh[64 * FEAT];            // fp16 routing diff W, [n][f] K-major
__device__ float g_part[4][BATCH * 64];        // routing logit partials (8 MB)
__device__ float g_lp[BATCH * 64];             // leaf probs (2 MB)

// ---------------- PTX helpers ----------------
__device__ __forceinline__ uint32_t smem_u32(const void* p) {
    uint32_t a;
    asm("{ .reg .u64 t; cvta.to.shared.u64 t, %1; cvt.u32.u64 %0, t; }" : "=r"(a) : "l"(p));
    return a;
}
__device__ __forceinline__ uint32_t elect_one() {
    uint32_t p;
    asm volatile("{\n\t.reg .pred p;\n\telect.sync _|p, 0xFFFFFFFF;\n\tselp.b32 %0, 1, 0, p;\n\t}" : "=r"(p));
    return p;
}

#define MBAR_INIT(a, c) asm volatile("mbarrier.init.shared.b64 [%0], %1;" ::"r"(a), "r"(c) : "memory")
#define MBAR_EXPECT_TX(a, n) asm volatile("mbarrier.arrive.expect_tx.shared.b64 _, [%0], %1;" ::"r"(a), "r"(n) : "memory")
#define MBAR_ARRIVE(a) asm volatile("mbarrier.arrive.shared.b64 _, [%0];" ::"r"(a) : "memory")

__device__ __forceinline__ void mbar_wait(uint32_t mbar, uint32_t parity) {
    uint32_t done;
    asm volatile(
        "{\n\t.reg .pred p;\n\t"
        "mbarrier.try_wait.parity.acquire.cta.shared::cta.b64 p, [%1], %2;\n\t"
        "selp.b32 %0, 1, 0, p;\n\t}"
        : "=r"(done) : "r"(mbar), "r"(parity) : "memory");
    if (!done) {
        asm volatile(
            "{\n\t.reg .pred P1;\n\t"
            "WL_%=:\n\t"
            "mbarrier.try_wait.parity.acquire.cta.shared::cta.b64 P1, [%0], %1, 0x989680;\n\t"
            "@P1 bra.uni WD_%=;\n\t"
            "bra.uni WL_%=;\n\t"
            "WD_%=:\n\t}"
            :: "r"(mbar), "r"(parity) : "memory");
    }
}

__device__ __forceinline__ void tma2d(uint32_t sa, const void* map, int cx, int cy, uint32_t mb) {
    asm volatile(
        "cp.async.bulk.tensor.2d.shared::cta.global.tile.mbarrier::complete_tx::bytes "
        "[%0], [%1, {%2, %3}], [%4];"
        :: "r"(sa), "l"(map), "r"(cx), "r"(cy), "r"(mb) : "memory");
}

__device__ __forceinline__ void ldm4(uint32_t* r, uint32_t addr) {
    asm volatile("ldmatrix.sync.aligned.m8n8.x4.shared.b16 {%0,%1,%2,%3}, [%4];"
        : "=r"(r[0]), "=r"(r[1]), "=r"(r[2]), "=r"(r[3]) : "r"(addr));
}
__device__ __forceinline__ void mma_f16(float* c, const uint32_t* a, uint32_t b0, uint32_t b1) {
    asm volatile(
        "mma.sync.aligned.m16n8k16.row.col.f32.f16.f16.f32 "
        "{%0,%1,%2,%3}, {%4,%5,%6,%7}, {%8,%9}, {%0,%1,%2,%3};\n"
        : "+f"(c[0]), "+f"(c[1]), "+f"(c[2]), "+f"(c[3])
        : "r"(a[0]), "r"(a[1]), "r"(a[2]), "r"(a[3]), "r"(b0), "r"(b1));
}

// ---------------- prep: fp32 -> fp16 (rn) ----------------
__global__ void k_cvt_h(const float4* __restrict__ src) {
    int i = blockIdx.x * blockDim.x + threadIdx.x;  // 2097152 threads = 8M floats
    float4 v = src[i];
    __half2 h0 = __floats2half2_rn(v.x, v.y);
    __half2 h1 = __floats2half2_rn(v.z, v.w);
    uint2 o;
    o.x = *(uint32_t*)&h0;
    o.y = *(uint32_t*)&h1;
    ((uint2*)g_xh)[i] = o;
}

// W transpose + fp16 round: lw[leaf][f][o] -> g_wh[leaf][o][f]
__global__ __launch_bounds__(256) void k_wt_h(const float* __restrict__ lw) {
    __shared__ __half sh[32][68];
    const int f0 = blockIdx.x * 64, o0 = blockIdx.y * 32, leaf = blockIdx.z;
    const int tid = threadIdx.x;
    const float* src = lw + (size_t)leaf * FEAT * LDIM;
    {
        int oj = tid & 31, fb = tid >> 5;
#pragma unroll
        for (int it = 0; it < 8; it++) {
            int fi = it * 8 + fb;
            sh[oj][fi] = __float2half_rn(src[(size_t)(f0 + fi) * LDIM + o0 + oj]);
        }
    }
    __syncthreads();
    __half* dst = g_wh + (size_t)leaf * LDIM * FEAT;
    {
        int fj = (tid & 15) * 4, ob = tid >> 4;
#pragma unroll
        for (int it = 0; it < 2; it++) {
            int oi = it * 16 + ob;
            uint2 v;
            v.x = *(const uint32_t*)&sh[oi][fj];
            v.y = *(const uint32_t*)&sh[oi][fj + 2];
            *(uint2*)(dst + (size_t)(o0 + oi) * FEAT + f0 + fj) = v;
        }
    }
}

// routing diff weights, fp16, [n][f] K-major
__global__ void k_dwh(const float* __restrict__ rw) {
    int i = blockIdx.x * blockDim.x + threadIdx.x;  // 65536
    int n = i >> 10, f = i & 1023;
    float v = 0.f;
    if (n < NINT) v = rw[(n * FEAT + f) * 2] - rw[(n * FEAT + f) * 2 + 1];
    g_dwh[n * FEAT + f] = __float2half_rn(v);
}

// ---------------- shared pipeline constants ----------------
#define BK 64
#define NSTAGE 3
#define A128_B 16384             // 128 rows x 128 bytes

// ---------------- routing GEMM: proven 288-thread body, split-K x4 (grid 64x4) ----------------
#define R_BSTAGE 8192                          // 64 rows x 128 bytes
#define R_OFF_B (NSTAGE * A128_B)              // 49152
#define R_OFF_MBAR (R_OFF_B + NSTAGE * R_BSTAGE)   // 73728
#define R_SMEM (R_OFF_MBAR + 64 + 1024)

__global__ __launch_bounds__(288, 2) void k_rgemm(
    const __grid_constant__ CUtensorMap tma_a,
    const __grid_constant__ CUtensorMap tma_b)
{
    extern __shared__ char smem_raw[];
    uint32_t sb = (smem_u32(smem_raw) + 1023u) & ~1023u;
    const int tid = threadIdx.x, lane = tid & 31, wid = tid >> 5;
    const int bm0 = blockIdx.x * 128;
    const int kb0 = blockIdx.y * 256;          // split-K base (256 halves per split)
    const int KT = (FEAT / 4) / BK;            // 4

    if (tid == 0) {
#pragma unroll
        for (int s = 0; s < NSTAGE; s++) {
            MBAR_INIT(sb + R_OFF_MBAR + s * 8, 1);
            MBAR_INIT(sb + R_OFF_MBAR + 24 + s * 8, 256);
        }
    }
    __syncthreads();

    if (wid == 8) {
        if (elect_one()) {
            int phase = 1, slot = 0;
            for (int s = 0; s < KT; s++) {
                mbar_wait(sb + R_OFF_MBAR + 24 + slot * 8, phase);
                MBAR_EXPECT_TX(sb + R_OFF_MBAR + slot * 8, A128_B + R_BSTAGE);
                tma2d(sb + slot * A128_B, &tma_a, kb0 + s * BK, bm0, sb + R_OFF_MBAR + slot * 8);
                tma2d(sb + R_OFF_B + slot * R_BSTAGE, &tma_b, kb0 + s * BK, 0,
                      sb + R_OFF_MBAR + slot * 8);
                if (++slot == NSTAGE) { slot = 0; phase ^= 1; }
            }
        }
        return;
    }

    const int mw = wid * 16;
    const int g = lane >> 2, cc = lane & 3;
    const int lr = lane & 7, grp = lane >> 3;
    const uint32_t xr = (uint32_t)lr << 4;
    const uint32_t a_rbase = (mw + (grp & 1) * 8 + lr) * 128;
    const uint32_t b_rbase = ((grp >> 1) * 8 + lr) * 128;
    const uint32_t a_cb0 = (uint32_t)(grp >> 1) * 16;
    const uint32_t b_cb0 = (uint32_t)(grp & 1) * 16;

    float acc[8][4];
#pragma unroll
    for (int b = 0; b < 8; b++)
#pragma unroll
        for (int c = 0; c < 4; c++) acc[b][c] = 0.f;

    int phase = 0, slot = 0;
    for (int kt = 0; kt < KT; kt++) {
        mbar_wait(sb + R_OFF_MBAR + slot * 8, phase);
        uint32_t abase = sb + slot * A128_B + a_rbase;
        uint32_t bbase = sb + R_OFF_B + slot * R_BSTAGE + b_rbase;
#pragma unroll
        for (int ks = 0; ks < 4; ks++) {
            uint32_t acb = (a_cb0 + ks * 32) ^ xr;
            uint32_t bcb = (b_cb0 + ks * 32) ^ xr;
            uint32_t a[4], b[4][4];
            ldm4(a, abase + acb);
#pragma unroll
            for (int pn = 0; pn < 4; pn++)
                ldm4(b[pn], bbase + pn * 16 * 128 + bcb);
#pragma unroll
            for (int nt = 0; nt < 8; nt++) {
                int pn = nt >> 1, hi = (nt & 1) << 1;
                mma_f16(acc[nt], a, b[pn][hi], b[pn][hi + 1]);
            }
        }
        MBAR_ARRIVE(sb + R_OFF_MBAR + 24 + slot * 8);
        if (++slot == NSTAGE) { slot = 0; phase ^= 1; }
    }

    float* dst = g_part[blockIdx.y];
    int r0 = bm0 + mw + g;
#pragma unroll
    for (int nt = 0; nt < 8; nt++) {
        int col = nt * 8 + 2 * cc;
        *(float2*)(dst + (size_t)r0 * 64 + col) = make_float2(acc[nt][0], acc[nt][1]);
        *(float2*)(dst + (size_t)(r0 + 8) * 64 + col) = make_float2(acc[nt][2], acc[nt][3]);
    }
}

// ---------------- leaf probs (separate proven kernel; sums split-K partials in fixed order) ----------------
__global__ void k_leaf() {
    __shared__ float ps[8][64];
    int tid = threadIdx.x;  // 512
    int rb = blockIdx.x * 8;
    int r = tid >> 6, n = tid & 63;
    if (n < NINT) {
        size_t idx = (size_t)(rb + r) * 64 + n;
        float s = (g_part[0][idx] + g_part[1][idx]) + (g_part[2][idx] + g_part[3][idx]);
        ps[r][n] = 1.f / (1.f + __expf(-s));
    }
    __syncthreads();
    int l = n;
    float prob = 1.f;
#pragma unroll
    for (int d = 0; d < 6; d++) {
        int node = (1 << d) - 1 + (l >> (6 - d));
        int dir = (l >> (5 - d)) & 1;
        float p = ps[r][node];
        prob *= dir ? (1.f - p) : p;
    }
    g_lp[(size_t)(rb + r) * 64 + l] = prob;
}

// ---------------- main GEMM (R11-exact): fp16 mma.sync + TMA, 8 warps of 32x64 ----------------
#define OFF_BSTG (NSTAGE * A128_B)         // 49152
#define OFF_MBAR (2 * NSTAGE * A128_B)     // 98304: full[3], empty[3]
#define SMEM_RAW (OFF_MBAR + 64 + 1024)

__global__ __launch_bounds__(288, 2) void k_main(
    const __grid_constant__ CUtensorMap tma_a,
    const __grid_constant__ CUtensorMap tma_b,
    const float* __restrict__ bias, float* __restrict__ out)
{
    extern __shared__ char smem_raw[];
    uint32_t sb = (smem_u32(smem_raw) + 1023u) & ~1023u;
    const int tid = threadIdx.x, lane = tid & 31, wid = tid >> 5;
    const int leaf = blockIdx.x;
    const int bm0 = blockIdx.y * 128;

    if (tid == 0) {
#pragma unroll
        for (int s = 0; s < NSTAGE; s++) {
            MBAR_INIT(sb + OFF_MBAR + s * 8, 1);
            MBAR_INIT(sb + OFF_MBAR + 24 + s * 8, 256);
        }
    }
    __syncthreads();

    if (wid == 8) {
        if (elect_one()) {
            int phase = 1, slot = 0;
            for (int s = 0; s < FEAT / BK; s++) {
                mbar_wait(sb + OFF_MBAR + 24 + slot * 8, phase);
                MBAR_EXPECT_TX(sb + OFF_MBAR + slot * 8, 2 * A128_B);
                tma2d(sb + slot * A128_B, &tma_a, s * BK, bm0, sb + OFF_MBAR + slot * 8);
                tma2d(sb + OFF_BSTG + slot * A128_B, &tma_b, s * BK, leaf * 128,
                      sb + OFF_MBAR + slot * 8);
                if (++slot == NSTAGE) { slot = 0; phase ^= 1; }
            }
        }
        return;
    }

    // 8 compute warps: 32x64 tile each (proven body)
    const int mw = (wid & 3) * 32, nw = (wid >> 2) * 64;
    const int g = lane >> 2, cc = lane & 3;
    const int lr = lane & 7, grp = lane >> 3;
    const uint32_t xr = (uint32_t)lr << 4;
    const uint32_t a_rbase = (mw + (grp & 1) * 8 + lr) * 128;
    const uint32_t b_rbase = (nw + (grp >> 1) * 8 + lr) * 128;
    const uint32_t a_cb0 = (uint32_t)(grp >> 1) * 16;
    const uint32_t b_cb0 = (uint32_t)(grp & 1) * 16;

    float acc[2][8][4];
#pragma unroll
    for (int a = 0; a < 2; a++)
#pragma unroll
        for (int b = 0; b < 8; b++)
#pragma unroll
            for (int c = 0; c < 4; c++) acc[a][b][c] = 0.f;

    int phase = 0, slot = 0;
    for (int kt = 0; kt < FEAT / BK; kt++) {
        mbar_wait(sb + OFF_MBAR + slot * 8, phase);
        uint32_t abase = sb + slot * A128_B + a_rbase;
        uint32_t bbase = sb + OFF_BSTG + slot * A128_B + b_rbase;
#pragma unroll
        for (int ks = 0; ks < 4; ks++) {
            uint32_t acb = (a_cb0 + ks * 32) ^ xr;
            uint32_t bcb = (b_cb0 + ks * 32) ^ xr;
            uint32_t a[2][4], b[4][4];
            ldm4(a[0], abase + acb);
            ldm4(a[1], abase + 16 * 128 + acb);
#pragma unroll
            for (int pn = 0; pn < 4; pn++)
                ldm4(b[pn], bbase + pn * 16 * 128 + bcb);
#pragma unroll
            for (int nt = 0; nt < 8; nt++) {
                int pn = nt >> 1, hi = (nt & 1) << 1;
                mma_f16(acc[0][nt], a[0], b[pn][hi], b[pn][hi + 1]);
                mma_f16(acc[1][nt], a[1], b[pn][hi], b[pn][hi + 1]);
            }
        }
        MBAR_ARRIVE(sb + OFF_MBAR + 24 + slot * 8);
        if (++slot == NSTAGE) { slot = 0; phase ^= 1; }
    }

#pragma unroll
    for (int mt = 0; mt < 2; mt++) {
        int r0 = bm0 + mw + mt * 16 + g;
        float p0 = g_lp[(size_t)r0 * 64 + leaf];
        float p1 = g_lp[(size_t)(r0 + 8) * 64 + leaf];
#pragma unroll
        for (int nt = 0; nt < 8; nt++) {
            int col = nw + nt * 8 + 2 * cc;
            float b0 = bias[leaf * LDIM + col];
            float b1 = bias[leaf * LDIM + col + 1];
            int gc = leaf * LDIM + col;
            float2 v0 = make_float2(p0 * (acc[mt][nt][0] + b0), p0 * (acc[mt][nt][1] + b1));
            float2 v1 = make_float2(p1 * (acc[mt][nt][2] + b0), p1 * (acc[mt][nt][3] + b1));
            *(float2*)(out + (size_t)r0 * OUTD + gc) = v0;
            *(float2*)(out + (size_t)(r0 + 8) * OUTD + gc) = v1;
        }
    }
}

// ---------------- host ----------------
typedef CUresult (*PFN_encodeTiled)(CUtensorMap*, CUtensorMapDataType, cuuint32_t, void*,
                                    const cuuint64_t*, const cuuint64_t*, const cuuint32_t*,
                                    const cuuint32_t*, CUtensorMapInterleave, CUtensorMapSwizzle,
                                    CUtensorMapL2promotion, CUtensorMapFloatOOBfill);

static void make_map(PFN_encodeTiled enc, CUtensorMap* m, void* base,
                     cuuint64_t rows, cuuint32_t box_rows) {
    cuuint64_t dims[2] = {FEAT, rows};
    cuuint64_t strides[1] = {FEAT * sizeof(__half)};
    cuuint32_t box[2] = {BK, box_rows};
    cuuint32_t es[2] = {1, 1};
    enc(m, CU_TENSOR_MAP_DATA_TYPE_UINT16, 2, base, dims, strides, box, es,
        CU_TENSOR_MAP_INTERLEAVE_NONE, CU_TENSOR_MAP_SWIZZLE_128B,
        CU_TENSOR_MAP_L2_PROMOTION_L2_128B, CU_TENSOR_MAP_FLOAT_OOB_FILL_NONE);
}

extern "C" void kernel_launch(void* const* d_in, const int* in_sizes, int n_in,
                              void* d_out, int out_size) {
    const float* x  = (const float*)d_in[0];
    const float* rw = (const float*)d_in[1];
    const float* lw = (const float*)d_in[2];
    const float* lb = (const float*)d_in[3];
    float* out = (float*)d_out;
    (void)in_sizes; (void)n_in; (void)out_size;

    PFN_encodeTiled enc = nullptr;
    cudaDriverEntryPointQueryResult qr;
    cudaGetDriverEntryPoint("cuTensorMapEncodeTiled", (void**)&enc, cudaEnableDefault, &qr);

    void* xh_ptr = nullptr; void* wh_ptr = nullptr; void* dwh_ptr = nullptr;
    cudaGetSymbolAddress(&xh_ptr, g_xh);
    cudaGetSymbolAddress(&wh_ptr, g_wh);
    cudaGetSymbolAddress(&dwh_ptr, g_dwh);

    CUtensorMap tma_a, tma_b, tma_d;
    make_map(enc, &tma_a, xh_ptr, 8192, 128);
    make_map(enc, &tma_b, wh_ptr, 8192, 128);
    make_map(enc, &tma_d, dwh_ptr, 64, 64);

    cudaFuncSetAttribute(k_main, cudaFuncAttributeMaxDynamicSharedMemorySize, SMEM_RAW);
    cudaFuncSetAttribute(k_rgemm, cudaFuncAttributeMaxDynamicSharedMemorySize, R_SMEM);

    // single-stream chain (deterministic, capture-safe)
    k_cvt_h<<<8192, 256>>>((const float4*)x);
    k_wt_h<<<dim3(16, 4, 64), 256>>>(lw);
    k_dwh<<<256, 256>>>(rw);
    k_rgemm<<<dim3(64, 4), 288, R_SMEM>>>(tma_a, tma_d);
    k_leaf<<<1024, 512>>>();
    k_main<<<dim3(64, 64), 288, SMEM_RAW>>>(tma_a, tma_b, lb, out);
}

// round 17
// speedup vs baseline: 1.0518x; 1.0063x over previous
#include <cuda_runtime.h>
#include <cuda.h>
#include <cuda_fp16.h>
#include <cstdint>

#define BATCH 8192
#define FEAT  1024
#define NLEAF 64
#define LDIM  128
#define OUTD  8192
#define NINT  63

// ---------------- device scratch (no allocations) ----------------
__device__ __half g_xh[BATCH * FEAT];          // fp16 x, row-major [8192][1024]   (16 MB)
__device__ __half g_wh[NLEAF * LDIM * FEAT];   // fp16 W^T, [leaf][o][f]           (16 MB)
__device__ __half g_dwh[64 * FEAT];            // fp16 routing diff W, [n][f] K-major
__device__ float g_part[4][BATCH * 64];        // routing logit partials (8 MB)
__device__ float g_lp[BATCH * 64];             // leaf probs (2 MB)

// ---------------- PTX helpers ----------------
__device__ __forceinline__ uint32_t smem_u32(const void* p) {
    uint32_t a;
    asm("{ .reg .u64 t; cvta.to.shared.u64 t, %1; cvt.u32.u64 %0, t; }" : "=r"(a) : "l"(p));
    return a;
}
__device__ __forceinline__ uint32_t elect_one() {
    uint32_t p;
    asm volatile("{\n\t.reg .pred p;\n\telect.sync _|p, 0xFFFFFFFF;\n\tselp.b32 %0, 1, 0, p;\n\t}" : "=r"(p));
    return p;
}

#define MBAR_INIT(a, c) asm volatile("mbarrier.init.shared.b64 [%0], %1;" ::"r"(a), "r"(c) : "memory")
#define MBAR_EXPECT_TX(a, n) asm volatile("mbarrier.arrive.expect_tx.shared.b64 _, [%0], %1;" ::"r"(a), "r"(n) : "memory")
#define MBAR_ARRIVE(a) asm volatile("mbarrier.arrive.shared.b64 _, [%0];" ::"r"(a) : "memory")

__device__ __forceinline__ void mbar_wait(uint32_t mbar, uint32_t parity) {
    uint32_t done;
    asm volatile(
        "{\n\t.reg .pred p;\n\t"
        "mbarrier.try_wait.parity.acquire.cta.shared::cta.b64 p, [%1], %2;\n\t"
        "selp.b32 %0, 1, 0, p;\n\t}"
        : "=r"(done) : "r"(mbar), "r"(parity) : "memory");
    if (!done) {
        asm volatile(
            "{\n\t.reg .pred P1;\n\t"
            "WL_%=:\n\t"
            "mbarrier.try_wait.parity.acquire.cta.shared::cta.b64 P1, [%0], %1, 0x989680;\n\t"
            "@P1 bra.uni WD_%=;\n\t"
            "bra.uni WL_%=;\n\t"
            "WD_%=:\n\t}"
            :: "r"(mbar), "r"(parity) : "memory");
    }
}

__device__ __forceinline__ void tma2d(uint32_t sa, const void* map, int cx, int cy, uint32_t mb) {
    asm volatile(
        "cp.async.bulk.tensor.2d.shared::cta.global.tile.mbarrier::complete_tx::bytes "
        "[%0], [%1, {%2, %3}], [%4];"
        :: "r"(sa), "l"(map), "r"(cx), "r"(cy), "r"(mb) : "memory");
}

__device__ __forceinline__ void ldm4(uint32_t* r, uint32_t addr) {
    asm volatile("ldmatrix.sync.aligned.m8n8.x4.shared.b16 {%0,%1,%2,%3}, [%4];"
        : "=r"(r[0]), "=r"(r[1]), "=r"(r[2]), "=r"(r[3]) : "r"(addr));
}
__device__ __forceinline__ void mma_f16(float* c, const uint32_t* a, uint32_t b0, uint32_t b1) {
    asm volatile(
        "mma.sync.aligned.m16n8k16.row.col.f32.f16.f16.f32 "
        "{%0,%1,%2,%3}, {%4,%5,%6,%7}, {%8,%9}, {%0,%1,%2,%3};\n"
        : "+f"(c[0]), "+f"(c[1]), "+f"(c[2]), "+f"(c[3])
        : "r"(a[0]), "r"(a[1]), "r"(a[2]), "r"(a[3]), "r"(b0), "r"(b1));
}

// streaming (evict-first) 8-byte store: output is write-once, keep it out of L2
__device__ __forceinline__ void stg_cs_f2(float* p, float x, float y) {
    asm volatile("st.global.cs.v2.f32 [%0], {%1, %2};" ::"l"(p), "f"(x), "f"(y) : "memory");
}

// ---------------- prep: fp32 -> fp16 (rn) ----------------
__global__ void k_cvt_h(const float4* __restrict__ src) {
    int i = blockIdx.x * blockDim.x + threadIdx.x;  // 2097152 threads = 8M floats
    float4 v = src[i];
    __half2 h0 = __floats2half2_rn(v.x, v.y);
    __half2 h1 = __floats2half2_rn(v.z, v.w);
    uint2 o;
    o.x = *(uint32_t*)&h0;
    o.y = *(uint32_t*)&h1;
    ((uint2*)g_xh)[i] = o;
}

// W transpose + fp16 round: lw[leaf][f][o] -> g_wh[leaf][o][f]
__global__ __launch_bounds__(256) void k_wt_h(const float* __restrict__ lw) {
    __shared__ __half sh[32][68];
    const int f0 = blockIdx.x * 64, o0 = blockIdx.y * 32, leaf = blockIdx.z;
    const int tid = threadIdx.x;
    const float* src = lw + (size_t)leaf * FEAT * LDIM;
    {
        int oj = tid & 31, fb = tid >> 5;
#pragma unroll
        for (int it = 0; it < 8; it++) {
            int fi = it * 8 + fb;
            sh[oj][fi] = __float2half_rn(src[(size_t)(f0 + fi) * LDIM + o0 + oj]);
        }
    }
    __syncthreads();
    __half* dst = g_wh + (size_t)leaf * LDIM * FEAT;
    {
        int fj = (tid & 15) * 4, ob = tid >> 4;
#pragma unroll
        for (int it = 0; it < 2; it++) {
            int oi = it * 16 + ob;
            uint2 v;
            v.x = *(const uint32_t*)&sh[oi][fj];
            v.y = *(const uint32_t*)&sh[oi][fj + 2];
            *(uint2*)(dst + (size_t)(o0 + oi) * FEAT + f0 + fj) = v;
        }
    }
}

// routing diff weights, fp16, [n][f] K-major
__global__ void k_dwh(const float* __restrict__ rw) {
    int i = blockIdx.x * blockDim.x + threadIdx.x;  // 65536
    int n = i >> 10, f = i & 1023;
    float v = 0.f;
    if (n < NINT) v = rw[(n * FEAT + f) * 2] - rw[(n * FEAT + f) * 2 + 1];
    g_dwh[n * FEAT + f] = __float2half_rn(v);
}

// ---------------- shared pipeline constants ----------------
#define BK 64
#define NSTAGE 3
#define A128_B 16384             // 128 rows x 128 bytes

// ---------------- routing GEMM: proven 288-thread body, split-K x4 (grid 64x4) ----------------
#define R_BSTAGE 8192                          // 64 rows x 128 bytes
#define R_OFF_B (NSTAGE * A128_B)              // 49152
#define R_OFF_MBAR (R_OFF_B + NSTAGE * R_BSTAGE)   // 73728
#define R_SMEM (R_OFF_MBAR + 64 + 1024)

__global__ __launch_bounds__(288, 2) void k_rgemm(
    const __grid_constant__ CUtensorMap tma_a,
    const __grid_constant__ CUtensorMap tma_b)
{
    extern __shared__ char smem_raw[];
    uint32_t sb = (smem_u32(smem_raw) + 1023u) & ~1023u;
    const int tid = threadIdx.x, lane = tid & 31, wid = tid >> 5;
    const int bm0 = blockIdx.x * 128;
    const int kb0 = blockIdx.y * 256;          // split-K base (256 halves per split)
    const int KT = (FEAT / 4) / BK;            // 4

    if (tid == 0) {
#pragma unroll
        for (int s = 0; s < NSTAGE; s++) {
            MBAR_INIT(sb + R_OFF_MBAR + s * 8, 1);
            MBAR_INIT(sb + R_OFF_MBAR + 24 + s * 8, 256);
        }
    }
    __syncthreads();

    if (wid == 8) {
        if (elect_one()) {
            int phase = 1, slot = 0;
            for (int s = 0; s < KT; s++) {
                mbar_wait(sb + R_OFF_MBAR + 24 + slot * 8, phase);
                MBAR_EXPECT_TX(sb + R_OFF_MBAR + slot * 8, A128_B + R_BSTAGE);
                tma2d(sb + slot * A128_B, &tma_a, kb0 + s * BK, bm0, sb + R_OFF_MBAR + slot * 8);
                tma2d(sb + R_OFF_B + slot * R_BSTAGE, &tma_b, kb0 + s * BK, 0,
                      sb + R_OFF_MBAR + slot * 8);
                if (++slot == NSTAGE) { slot = 0; phase ^= 1; }
            }
        }
        return;
    }

    const int mw = wid * 16;
    const int g = lane >> 2, cc = lane & 3;
    const int lr = lane & 7, grp = lane >> 3;
    const uint32_t xr = (uint32_t)lr << 4;
    const uint32_t a_rbase = (mw + (grp & 1) * 8 + lr) * 128;
    const uint32_t b_rbase = ((grp >> 1) * 8 + lr) * 128;
    const uint32_t a_cb0 = (uint32_t)(grp >> 1) * 16;
    const uint32_t b_cb0 = (uint32_t)(grp & 1) * 16;

    float acc[8][4];
#pragma unroll
    for (int b = 0; b < 8; b++)
#pragma unroll
        for (int c = 0; c < 4; c++) acc[b][c] = 0.f;

    int phase = 0, slot = 0;
    for (int kt = 0; kt < KT; kt++) {
        mbar_wait(sb + R_OFF_MBAR + slot * 8, phase);
        uint32_t abase = sb + slot * A128_B + a_rbase;
        uint32_t bbase = sb + R_OFF_B + slot * R_BSTAGE + b_rbase;
#pragma unroll
        for (int ks = 0; ks < 4; ks++) {
            uint32_t acb = (a_cb0 + ks * 32) ^ xr;
            uint32_t bcb = (b_cb0 + ks * 32) ^ xr;
            uint32_t a[4], b[4][4];
            ldm4(a, abase + acb);
#pragma unroll
            for (int pn = 0; pn < 4; pn++)
                ldm4(b[pn], bbase + pn * 16 * 128 + bcb);
#pragma unroll
            for (int nt = 0; nt < 8; nt++) {
                int pn = nt >> 1, hi = (nt & 1) << 1;
                mma_f16(acc[nt], a, b[pn][hi], b[pn][hi + 1]);
            }
        }
        MBAR_ARRIVE(sb + R_OFF_MBAR + 24 + slot * 8);
        if (++slot == NSTAGE) { slot = 0; phase ^= 1; }
    }

    float* dst = g_part[blockIdx.y];
    int r0 = bm0 + mw + g;
#pragma unroll
    for (int nt = 0; nt < 8; nt++) {
        int col = nt * 8 + 2 * cc;
        *(float2*)(dst + (size_t)r0 * 64 + col) = make_float2(acc[nt][0], acc[nt][1]);
        *(float2*)(dst + (size_t)(r0 + 8) * 64 + col) = make_float2(acc[nt][2], acc[nt][3]);
    }
}

// ---------------- leaf probs (sums split-K partials in fixed order) ----------------
__global__ void k_leaf() {
    __shared__ float ps[8][64];
    int tid = threadIdx.x;  // 512
    int rb = blockIdx.x * 8;
    int r = tid >> 6, n = tid & 63;
    if (n < NINT) {
        size_t idx = (size_t)(rb + r) * 64 + n;
        float s = (g_part[0][idx] + g_part[1][idx]) + (g_part[2][idx] + g_part[3][idx]);
        ps[r][n] = 1.f / (1.f + __expf(-s));
    }
    __syncthreads();
    int l = n;
    float prob = 1.f;
#pragma unroll
    for (int d = 0; d < 6; d++) {
        int node = (1 << d) - 1 + (l >> (6 - d));
        int dir = (l >> (5 - d)) & 1;
        float p = ps[r][node];
        prob *= dir ? (1.f - p) : p;
    }
    g_lp[(size_t)(rb + r) * 64 + l] = prob;
}

// ---------------- main GEMM (R11-exact pipeline; streaming epilogue stores) ----------------
#define OFF_BSTG (NSTAGE * A128_B)         // 49152
#define OFF_MBAR (2 * NSTAGE * A128_B)     // 98304: full[3], empty[3]
#define SMEM_RAW (OFF_MBAR + 64 + 1024)

__global__ __launch_bounds__(288, 2) void k_main(
    const __grid_constant__ CUtensorMap tma_a,
    const __grid_constant__ CUtensorMap tma_b,
    const float* __restrict__ bias, float* __restrict__ out)
{
    extern __shared__ char smem_raw[];
    uint32_t sb = (smem_u32(smem_raw) + 1023u) & ~1023u;
    const int tid = threadIdx.x, lane = tid & 31, wid = tid >> 5;
    const int leaf = blockIdx.x;
    const int bm0 = blockIdx.y * 128;

    if (tid == 0) {
#pragma unroll
        for (int s = 0; s < NSTAGE; s++) {
            MBAR_INIT(sb + OFF_MBAR + s * 8, 1);
            MBAR_INIT(sb + OFF_MBAR + 24 + s * 8, 256);
        }
    }
    __syncthreads();

    if (wid == 8) {
        if (elect_one()) {
            int phase = 1, slot = 0;
            for (int s = 0; s < FEAT / BK; s++) {
                mbar_wait(sb + OFF_MBAR + 24 + slot * 8, phase);
                MBAR_EXPECT_TX(sb + OFF_MBAR + slot * 8, 2 * A128_B);
                tma2d(sb + slot * A128_B, &tma_a, s * BK, bm0, sb + OFF_MBAR + slot * 8);
                tma2d(sb + OFF_BSTG + slot * A128_B, &tma_b, s * BK, leaf * 128,
                      sb + OFF_MBAR + slot * 8);
                if (++slot == NSTAGE) { slot = 0; phase ^= 1; }
            }
        }
        return;
    }

    // 8 compute warps: 32x64 tile each (proven body)
    const int mw = (wid & 3) * 32, nw = (wid >> 2) * 64;
    const int g = lane >> 2, cc = lane & 3;
    const int lr = lane & 7, grp = lane >> 3;
    const uint32_t xr = (uint32_t)lr << 4;
    const uint32_t a_rbase = (mw + (grp & 1) * 8 + lr) * 128;
    const uint32_t b_rbase = (nw + (grp >> 1) * 8 + lr) * 128;
    const uint32_t a_cb0 = (uint32_t)(grp >> 1) * 16;
    const uint32_t b_cb0 = (uint32_t)(grp & 1) * 16;

    float acc[2][8][4];
#pragma unroll
    for (int a = 0; a < 2; a++)
#pragma unroll
        for (int b = 0; b < 8; b++)
#pragma unroll
            for (int c = 0; c < 4; c++) acc[a][b][c] = 0.f;

    int phase = 0, slot = 0;
    for (int kt = 0; kt < FEAT / BK; kt++) {
        mbar_wait(sb + OFF_MBAR + slot * 8, phase);
        uint32_t abase = sb + slot * A128_B + a_rbase;
        uint32_t bbase = sb + OFF_BSTG + slot * A128_B + b_rbase;
#pragma unroll
        for (int ks = 0; ks < 4; ks++) {
            uint32_t acb = (a_cb0 + ks * 32) ^ xr;
            uint32_t bcb = (b_cb0 + ks * 32) ^ xr;
            uint32_t a[2][4], b[4][4];
            ldm4(a[0], abase + acb);
            ldm4(a[1], abase + 16 * 128 + acb);
#pragma unroll
            for (int pn = 0; pn < 4; pn++)
                ldm4(b[pn], bbase + pn * 16 * 128 + bcb);
#pragma unroll
            for (int nt = 0; nt < 8; nt++) {
                int pn = nt >> 1, hi = (nt & 1) << 1;
                mma_f16(acc[0][nt], a[0], b[pn][hi], b[pn][hi + 1]);
                mma_f16(acc[1][nt], a[1], b[pn][hi], b[pn][hi + 1]);
            }
        }
        MBAR_ARRIVE(sb + OFF_MBAR + 24 + slot * 8);
        if (++slot == NSTAGE) { slot = 0; phase ^= 1; }
    }

#pragma unroll
    for (int mt = 0; mt < 2; mt++) {
        int r0 = bm0 + mw + mt * 16 + g;
        float p0 = g_lp[(size_t)r0 * 64 + leaf];
        float p1 = g_lp[(size_t)(r0 + 8) * 64 + leaf];
#pragma unroll
        for (int nt = 0; nt < 8; nt++) {
            int col = nw + nt * 8 + 2 * cc;
            float b0 = bias[leaf * LDIM + col];
            float b1 = bias[leaf * LDIM + col + 1];
            int gc = leaf * LDIM + col;
            stg_cs_f2(out + (size_t)r0 * OUTD + gc,
                      p0 * (acc[mt][nt][0] + b0), p0 * (acc[mt][nt][1] + b1));
            stg_cs_f2(out + (size_t)(r0 + 8) * OUTD + gc,
                      p1 * (acc[mt][nt][2] + b0), p1 * (acc[mt][nt][3] + b1));
        }
    }
}

// ---------------- host ----------------
typedef CUresult (*PFN_encodeTiled)(CUtensorMap*, CUtensorMapDataType, cuuint32_t, void*,
                                    const cuuint64_t*, const cuuint64_t*, const cuuint32_t*,
                                    const cuuint32_t*, CUtensorMapInterleave, CUtensorMapSwizzle,
                                    CUtensorMapL2promotion, CUtensorMapFloatOOBfill);

static void make_map(PFN_encodeTiled enc, CUtensorMap* m, void* base,
                     cuuint64_t rows, cuuint32_t box_rows) {
    cuuint64_t dims[2] = {FEAT, rows};
    cuuint64_t strides[1] = {FEAT * sizeof(__half)};
    cuuint32_t box[2] = {BK, box_rows};
    cuuint32_t es[2] = {1, 1};
    enc(m, CU_TENSOR_MAP_DATA_TYPE_UINT16, 2, base, dims, strides, box, es,
        CU_TENSOR_MAP_INTERLEAVE_NONE, CU_TENSOR_MAP_SWIZZLE_128B,
        CU_TENSOR_MAP_L2_PROMOTION_L2_128B, CU_TENSOR_MAP_FLOAT_OOB_FILL_NONE);
}

extern "C" void kernel_launch(void* const* d_in, const int* in_sizes, int n_in,
                              void* d_out, int out_size) {
    const float* x  = (const float*)d_in[0];
    const float* rw = (const float*)d_in[1];
    const float* lw = (const float*)d_in[2];
    const float* lb = (const float*)d_in[3];
    float* out = (float*)d_out;
    (void)in_sizes; (void)n_in; (void)out_size;

    PFN_encodeTiled enc = nullptr;
    cudaDriverEntryPointQueryResult qr;
    cudaGetDriverEntryPoint("cuTensorMapEncodeTiled", (void**)&enc, cudaEnableDefault, &qr);

    void* xh_ptr = nullptr; void* wh_ptr = nullptr; void* dwh_ptr = nullptr;
    cudaGetSymbolAddress(&xh_ptr, g_xh);
    cudaGetSymbolAddress(&wh_ptr, g_wh);
    cudaGetSymbolAddress(&dwh_ptr, g_dwh);

    CUtensorMap tma_a, tma_b, tma_d;
    make_map(enc, &tma_a, xh_ptr, 8192, 128);
    make_map(enc, &tma_b, wh_ptr, 8192, 128);
    make_map(enc, &tma_d, dwh_ptr, 64, 64);

    cudaFuncSetAttribute(k_main, cudaFuncAttributeMaxDynamicSharedMemorySize, SMEM_RAW);
    cudaFuncSetAttribute(k_rgemm, cudaFuncAttributeMaxDynamicSharedMemorySize, R_SMEM);

    // single-stream chain (deterministic, capture-safe)
    k_cvt_h<<<8192, 256>>>((const float4*)x);
    k_wt_h<<<dim3(16, 4, 64), 256>>>(lw);
    k_dwh<<<256, 256>>>(rw);
    k_rgemm<<<dim3(64, 4), 288, R_SMEM>>>(tma_a, tma_d);
    k_leaf<<<1024, 512>>>();
    k_main<<<dim3(64, 64), 288, SMEM_RAW>>>(tma_a, tma_b, lb, out);
}